// round 13
// baseline (speedup 1.0000x reference)
#include <cuda_runtime.h>
#include <mma.h>
#include <cstdint>
#include <cstddef>

using namespace nvcuda;

#define Bb 32
#define Ss 2048
#define Ii 256
#define Hh 256
#define G4 1024   // 4*H

__device__ __align__(16) float g_P[(size_t)Bb * Ss * G4];

// ---------------- helpers ----------------
__device__ __forceinline__ void ffma2(unsigned long long &d, unsigned long long a, unsigned long long b) {
    asm volatile("fma.rn.f32x2 %0, %1, %2, %0;" : "+l"(d) : "l"(a), "l"(b));
}
__device__ __forceinline__ unsigned long long pk2(float x, float y) {
    unsigned long long r; asm("mov.b64 %0, {%1, %2};" : "=l"(r) : "f"(x), "f"(y)); return r;
}
__device__ __forceinline__ float2 upk2(unsigned long long v) {
    float2 f; asm("mov.b64 {%0, %1}, %2;" : "=f"(f.x), "=f"(f.y) : "l"(v)); return f;
}
__device__ __forceinline__ float ex2f(float x) {
    float r; asm("ex2.approx.ftz.f32 %0, %1;" : "=f"(r) : "f"(x)); return r;
}
__device__ __forceinline__ float rcpf(float x) {
    float r; asm("rcp.approx.ftz.f32 %0, %1;" : "=f"(r) : "f"(x)); return r;
}
#define L2E 1.4426950408889634f
// tanh(x) = 1 - 2/(1+e^{2x})
__device__ __forceinline__ float tanh_f(float x) {
    return fmaf(-2.0f, rcpf(1.0f + ex2f(2.0f * L2E * x)), 1.0f);
}

__device__ __forceinline__ void cp16(void* dst, const void* src) {
    uint32_t d = (uint32_t)__cvta_generic_to_shared(dst);
    asm volatile("cp.async.cg.shared.global [%0], [%1], 16;" :: "r"(d), "l"(src) : "memory");
}
// Poll at CTA scope (cheap). Data arrives via st.async (async proxy); the
// cta-acquire on the flipped mbarrier makes it visible.
__device__ __forceinline__ void mbar_wait(uint32_t mbar, uint32_t parity) {
    asm volatile(
        "{\n\t.reg .pred P1;\n\t"
        "WAITL_%=:\n\t"
        "mbarrier.try_wait.parity.acquire.cta.shared::cta.b64 P1, [%0], %1, 0x989680;\n\t"
        "@!P1 bra WAITL_%=;\n\t}"
        :: "r"(mbar), "r"(parity) : "memory");
}
__device__ __forceinline__ void mbar_expect(uint32_t mbar, uint32_t bytes) {
    asm volatile("mbarrier.arrive.expect_tx.shared.b64 _, [%0], %1;"
                 :: "r"(mbar), "r"(bytes) : "memory");
}

// ---------------- kernel 1: x-projection GEMM (smem-staged tf32 wmma) ----------------
#define XK 16
#define NKC (Ii / XK)
__global__ __launch_bounds__(256, 2) void xproj_kernel(const float* __restrict__ x,
                                                       const float* __restrict__ W) {
    __shared__ __align__(16) float sA[2][128][XK + 4];
    __shared__ __align__(16) float sB[2][XK][128 + 4];

    const int tid = threadIdx.x;
    const int wid = tid >> 5;
    const int wm = wid & 3, wn = wid >> 2;
    const int m0 = blockIdx.y * 128;
    const int n0 = blockIdx.x * 128;

    wmma::fragment<wmma::accumulator, 16, 16, 8, float> acc[2][4];
#pragma unroll
    for (int i = 0; i < 2; i++)
#pragma unroll
        for (int j = 0; j < 4; j++) wmma::fill_fragment(acc[i][j], 0.0f);

    auto issue = [&](int buf, int kc) {
#pragma unroll
        for (int u = 0; u < 2; u++) {
            int v = tid + u * 256;
            int r = v >> 2, kq = v & 3;
            cp16(&sA[buf][r][4 * kq], x + (size_t)(m0 + r) * Ii + kc * XK + 4 * kq);
            int kr = v >> 5, cq = v & 31;
            cp16(&sB[buf][kr][4 * cq], W + (size_t)(kc * XK + kr) * G4 + n0 + 4 * cq);
        }
    };

    issue(0, 0);
    asm volatile("cp.async.commit_group;");

    for (int kc = 0; kc < NKC; kc++) {
        int buf = kc & 1;
        if (kc + 1 < NKC) {
            issue(buf ^ 1, kc + 1);
            asm volatile("cp.async.commit_group;");
            asm volatile("cp.async.wait_group 1;");
        } else {
            asm volatile("cp.async.wait_group 0;");
        }
        __syncthreads();
#pragma unroll
        for (int ks = 0; ks < XK; ks += 8) {
            wmma::fragment<wmma::matrix_a, 16, 16, 8, wmma::precision::tf32, wmma::row_major> af[2];
            wmma::fragment<wmma::matrix_b, 16, 16, 8, wmma::precision::tf32, wmma::row_major> bf[4];
#pragma unroll
            for (int i = 0; i < 2; i++) {
                wmma::load_matrix_sync(af[i], &sA[buf][wm * 32 + 16 * i][ks], XK + 4);
#pragma unroll
                for (int e = 0; e < af[i].num_elements; e++) af[i].x[e] = wmma::__float_to_tf32(af[i].x[e]);
            }
#pragma unroll
            for (int j = 0; j < 4; j++) {
                wmma::load_matrix_sync(bf[j], &sB[buf][ks][wn * 64 + 16 * j], 128 + 4);
#pragma unroll
                for (int e = 0; e < bf[j].num_elements; e++) bf[j].x[e] = wmma::__float_to_tf32(bf[j].x[e]);
            }
#pragma unroll
            for (int i = 0; i < 2; i++)
#pragma unroll
                for (int j = 0; j < 4; j++) wmma::mma_sync(acc[i][j], af[i], bf[j], acc[i][j]);
        }
        __syncthreads();
    }
#pragma unroll
    for (int i = 0; i < 2; i++)
#pragma unroll
        for (int j = 0; j < 4; j++)
            wmma::store_matrix_sync(g_P + (size_t)(m0 + wm * 32 + 16 * i) * G4 + n0 + wn * 64 + 16 * j,
                                    acc[i][j], G4, wmma::mem_row_major);
}

// ---------------- kernel 2: recurrent chain, interleaved batch phases ----------------
// 16 clusters x 8 CTAs, 2 batches/cluster, 512 thr/CTA. CTA owns 32 h-cols.
// The two batches run as SEPARATE phases per step (own h buffers + mbarriers):
//   waitA -> computeA -> storeA -> waitB -> computeB -> storeB
// so each chain's store->wait latency is hidden behind the other chain's
// compute (~600 cy). Lane map per phase: hc(1b)|grp(1b)|lk(3b); per lane
// 2 gates x 32 rows (rows 32i+4lk+{0..3}) = 32 FFMA2. Reduce: 6 xor-shfls.
// Task lanes (lk<2) do z-activation; comb lanes (lane&15)==2 (lanes 2,18)
// update c, store out, and push hnew to all 8 CTAs via 4-byte st.async with
// mbarrier complete_tx (1024 B/phase/batch). tid0 re-arms after each wait.
__global__ void __cluster_dims__(8, 1, 1) __launch_bounds__(512, 1)
lstm_rec(const float* __restrict__ W, const float* __restrict__ bias,
         const float* __restrict__ h0, const float* __restrict__ c0,
         float* __restrict__ out) {
    __shared__ __align__(16) float h_sm[4 * Hh];         // [batch*2+parity][256]
    __shared__ __align__(8) unsigned long long mbar[4];  // [batch*2+parity]

    const int tid = threadIdx.x;
    uint32_t rk; asm("mov.u32 %0, %%cluster_ctarank;" : "=r"(rk));
    const int b0 = (blockIdx.x >> 3) * 2;
    const int w = tid >> 5, lane = tid & 31;
    const int hc = lane >> 4, grp = (lane >> 3) & 1, lk = lane & 7;
    const int hcol = (int)rk * 32 + 2 * w + hc;

    // weights: gates grp*2, grp*2+1; rows 32i+4lk+{0..3} (same packing as R9)
    unsigned long long wreg[2][16];
#pragma unroll
    for (int gg = 0; gg < 2; gg++) {
        const float* Wc = W + (size_t)(grp * 2 + gg) * 256 + hcol;
#pragma unroll
        for (int i = 0; i < 8; i++) {
            const float* p = Wc + (size_t)(256 + 32 * i + 4 * lk) * G4;
            wreg[gg][2 * i]     = pk2(p[0], p[G4]);
            wreg[gg][2 * i + 1] = pk2(p[2 * (size_t)G4], p[3 * (size_t)G4]);
        }
    }

    // task lanes lk<2: gate gsel = grp*2 + (lk&1)  (clamped in-bounds for all)
    const int gsel = grp * 2 + (lk & 1);
    const float bv = bias[gsel * 256 + hcol];
    const size_t prowA = ((size_t)b0 * Ss) * G4 + gsel * 256 + hcol;
    const size_t prowB = ((size_t)(b0 + 1) * Ss) * G4 + gsel * 256 + hcol;
    const float ymL = (gsel == 2) ? 2.0f * L2E : -L2E;
    const float al  = (gsel == 2) ? 1.0f : 0.0f;
    const float be  = (gsel == 2) ? -2.0f : 1.0f;

    // comb lanes: lanes 2 (hc=0) and 18 (hc=1)
    const bool comb = ((lane & 15) == 2);
    float cregA = comb ? c0[(size_t)b0 * Hh + hcol] : 0.0f;
    float cregB = comb ? c0[(size_t)(b0 + 1) * Hh + hcol] : 0.0f;

    const uint32_t hbase = (uint32_t)__cvta_generic_to_shared(h_sm);
    const uint32_t mbase = (uint32_t)__cvta_generic_to_shared(mbar);
    const uint32_t mb_delta = mbase - hbase;   // same delta after mapa (same rank)
    uint32_t htgt[8];
#pragma unroll
    for (int rr = 0; rr < 8; rr++)
        asm("mapa.shared::cluster.u32 %0, %1, %2;" : "=r"(htgt[rr]) : "r"(hbase), "r"(rr));

    if (tid == 0) {
#pragma unroll
        for (int m = 0; m < 4; m++) {
            asm volatile("mbarrier.init.shared.b64 [%0], %1;" :: "r"(mbase + m * 8), "r"(1u) : "memory");
        }
#pragma unroll
        for (int m = 0; m < 4; m++) mbar_expect(mbase + m * 8, 1024u);
        asm volatile("fence.mbarrier_init.release.cluster;" ::: "memory");
    }
    {   // seed h(0) for both batches into parity-0 buffers
        int b = tid >> 8, r = tid & 255;
        h_sm[(b * 2) * Hh + r] = h0[(size_t)(b0 + b) * Hh + r];
    }
    asm volatile("barrier.cluster.arrive.aligned;" ::: "memory");
    asm volatile("barrier.cluster.wait.aligned;" ::: "memory");

    float pcA = g_P[prowA], pcB = g_P[prowB];

    for (int t = 0; t < Ss; t++) {
        const int par = t & 1;
        const uint32_t wph = ((uint32_t)(t - 1) >> 1) & 1u;
        const bool notlast = (t + 1 < Ss);
        const size_t tn = (size_t)(notlast ? t + 1 : t) * G4;

#pragma unroll
        for (int bx = 0; bx < 2; bx++) {    // phase A (bx=0), phase B (bx=1)
            const int buf = bx * 2 + par;
            const uint32_t mb = mbase + (uint32_t)(bx * 2 + par) * 8;
            if (t > 0) {
                mbar_wait(mb, wph);
                if (tid == 0) mbar_expect(mb, 1024u);   // re-arm for h(t+2)
            }
            float pf = bx ? g_P[prowB + tn] : g_P[prowA + tn];

            // ---- matvec: 2 gates, 1 batch, rows 32i+4lk+{0..3} ----
            unsigned long long a00 = 0, a01 = 0, a10 = 0, a11 = 0;
            const ulonglong2* hb = (const ulonglong2*)(h_sm + buf * Hh);
#pragma unroll
            for (int i = 0; i < 8; i++) {
                ulonglong2 v = hb[8 * i + lk];
                ffma2(a00, wreg[0][2 * i], v.x);  ffma2(a01, wreg[0][2 * i + 1], v.y);
                ffma2(a10, wreg[1][2 * i], v.x);  ffma2(a11, wreg[1][2 * i + 1], v.y);
            }
            float2 f;
            f = upk2(a00); float s0 = f.x + f.y; f = upk2(a01); s0 += f.x + f.y;
            f = upk2(a10); float s1 = f.x + f.y; f = upk2(a11); s1 += f.x + f.y;
#pragma unroll
            for (int d = 1; d <= 4; d <<= 1) {
                s0 += __shfl_xor_sync(0xffffffffu, s0, d);
                s1 += __shfl_xor_sync(0xffffffffu, s1, d);
            }
            // task lanes (lk<2): z = tanh(pre + P + b); then per-gate activation
            float pre = (lk & 1) ? s1 : s0;
            float pc = bx ? pcB : pcA;
            float z1 = tanh_f(pre + pc + bv);
            float act = fmaf(be, rcpf(1.0f + ex2f(ymL * z1)), al);
            if (bx) pcB = pf; else pcA = pf;

            // gather i,f,g,o for col hc: lanes hc*16 + {0,1,8,9}
            int base = (lane & 16);
            float ig_ = __shfl_sync(0xffffffffu, act, base);
            float fg_ = __shfl_sync(0xffffffffu, act, base + 1);
            float gg_ = __shfl_sync(0xffffffffu, act, base + 8);
            float og_ = __shfl_sync(0xffffffffu, act, base + 9);

            float creg = bx ? cregB : cregA;
            creg = fmaf(fg_, creg, ig_ * gg_);
            float hnew = tanh_f(creg) * og_;
            if (bx) cregB = creg; else cregA = creg;

            if (comb) {
                out[((size_t)(b0 + bx) * Ss + t) * Hh + hcol] = hnew;
                if (notlast) {
                    uint32_t off = (uint32_t)((bx * 2 + (par ^ 1)) * Hh + hcol) * 4;
                    uint32_t mboff = mb_delta + (uint32_t)(bx * 2 + (par ^ 1)) * 8;
#pragma unroll
                    for (int rr = 0; rr < 8; rr++)
                        asm volatile(
                            "st.async.weak.shared::cluster.mbarrier::complete_tx::bytes.f32 "
                            "[%0], %1, [%2];"
                            :: "r"(htgt[rr] + off), "f"(hnew), "r"(htgt[rr] + mboff) : "memory");
                }
            }
        }
    }
    asm volatile("barrier.cluster.arrive.aligned;" ::: "memory");
    asm volatile("barrier.cluster.wait.aligned;" ::: "memory");
}

// ---------------- kernel 3: zero trailing (1,B,H) outputs ----------------
__global__ void zero_tail(float* out, int total, int start) {
    int i = blockIdx.x * blockDim.x + threadIdx.x + start;
    if (i < total) out[i] = 0.0f;
}

extern "C" void kernel_launch(void* const* d_in, const int* in_sizes, int n_in,
                              void* d_out, int out_size) {
    const float* x    = (const float*)d_in[0];
    const float* h0   = (const float*)d_in[1];
    const float* c0   = (const float*)d_in[2];
    const float* W    = (const float*)d_in[3];
    const float* bias = (const float*)d_in[4];
    float* out = (float*)d_out;

    dim3 gx(G4 / 128, (Bb * Ss) / 128);
    xproj_kernel<<<gx, 256>>>(x, W);
    lstm_rec<<<128, 512>>>(W, bias, h0, c0, out);

    int main_elems = Bb * Ss * Hh;
    int tail = out_size - main_elems;
    if (tail > 0) zero_tail<<<(tail + 255) / 256, 256>>>(out, out_size, main_elems);
}